// round 1
// baseline (speedup 1.0000x reference)
#include <cuda_runtime.h>
#include <cstdint>
#include <cstddef>

#define NE    8
#define HID   2048
#define INTER 2816
#define NTOK  8192
#define MAXENT (NTOK * 2)

// ---------------- scratch (device globals; no runtime allocation) ----------------
__device__ int   g_count[NE];
__device__ int   g_cursor[NE];
__device__ int   g_off[NE];
__device__ int   g_tok_e[NTOK][2];
__device__ float g_tok_w[NTOK][2];
__device__ int   g_list_c[MAXENT];    // token*2 + slot
__device__ float g_list_w[MAXENT];
__device__ float g_h[(size_t)MAXENT * INTER];   // ~184 MB
__device__ float g_y[(size_t)MAXENT * HID];     // ~134 MB

// ---------------- helpers ----------------
__device__ __forceinline__ uint32_t f2tf(float x) {
    uint32_t r;
    asm("cvt.rna.tf32.f32 %0, %1;" : "=r"(r) : "f"(x));
    return r;
}

__device__ __forceinline__ void mma8(float* d, const uint32_t* a, const uint32_t* b) {
    asm volatile(
        "mma.sync.aligned.m16n8k8.row.col.f32.tf32.tf32.f32 "
        "{%0,%1,%2,%3}, {%4,%5,%6,%7}, {%8,%9}, {%0,%1,%2,%3};\n"
        : "+f"(d[0]), "+f"(d[1]), "+f"(d[2]), "+f"(d[3])
        : "r"(a[0]), "r"(a[1]), "r"(a[2]), "r"(a[3]),
          "r"(b[0]), "r"(b[1]));
}

// ---------------- 1. reset ----------------
__global__ void reset_kernel() {
    if (threadIdx.x < NE) g_count[threadIdx.x] = 0;
}

// ---------------- 2. gating: logits, softmax, top-2, counts ----------------
__global__ __launch_bounds__(256) void gate_kernel(const float* __restrict__ x,
                                                   const float* __restrict__ gw) {
    int warp = threadIdx.x >> 5;
    int lane = threadIdx.x & 31;
    int t = blockIdx.x * 8 + warp;
    if (t >= NTOK) return;

    const float4* xp = (const float4*)(x + (size_t)t * HID);
    float acc[NE];
#pragma unroll
    for (int e = 0; e < NE; e++) acc[e] = 0.f;

    for (int kk = 0; kk < HID / 4; kk += 32) {
        float4 xv = xp[kk + lane];
#pragma unroll
        for (int e = 0; e < NE; e++) {
            float4 g = ((const float4*)(gw + (size_t)e * HID))[kk + lane];
            acc[e] += xv.x * g.x + xv.y * g.y + xv.z * g.z + xv.w * g.w;
        }
    }
#pragma unroll
    for (int e = 0; e < NE; e++) {
#pragma unroll
        for (int o = 16; o > 0; o >>= 1)
            acc[e] += __shfl_xor_sync(0xffffffffu, acc[e], o);
    }
    if (lane == 0) {
        float mx = acc[0];
#pragma unroll
        for (int e = 1; e < NE; e++) mx = fmaxf(mx, acc[e]);
        float p[NE], s = 0.f;
#pragma unroll
        for (int e = 0; e < NE; e++) { p[e] = __expf(acc[e] - mx); s += p[e]; }
        float inv = 1.f / s;
        int i0 = 0; float v0 = p[0];
#pragma unroll
        for (int e = 1; e < NE; e++) if (p[e] > v0) { v0 = p[e]; i0 = e; }
        int i1 = -1; float v1 = -1.f;
#pragma unroll
        for (int e = 0; e < NE; e++) if (e != i0 && p[e] > v1) { v1 = p[e]; i1 = e; }
        g_tok_e[t][0] = i0; g_tok_e[t][1] = i1;
        g_tok_w[t][0] = v0 * inv; g_tok_w[t][1] = v1 * inv;
        atomicAdd(&g_count[i0], 1);
        atomicAdd(&g_count[i1], 1);
    }
}

// ---------------- 3. offsets ----------------
__global__ void offsets_kernel() {
    if (threadIdx.x == 0 && blockIdx.x == 0) {
        int s = 0;
        for (int e = 0; e < NE; e++) {
            g_off[e] = s;
            s += g_count[e];
            g_cursor[e] = 0;
        }
    }
}

// ---------------- 4. scatter tokens into packed per-expert lists ----------------
__global__ void scatter_kernel() {
    int t = blockIdx.x * blockDim.x + threadIdx.x;
    if (t >= NTOK) return;
#pragma unroll
    for (int s = 0; s < 2; s++) {
        int e = g_tok_e[t][s];
        int pos = atomicAdd(&g_cursor[e], 1);
        int idx = g_off[e] + pos;
        g_list_c[idx] = t * 2 + s;
        g_list_w[idx] = g_tok_w[t][s];
    }
}

// ---------------- 5. GEMM1: h = silu(X W_g^T) * (X W_u^T), gathered rows ----------------
// Block: 128 rows x (64 g-cols + 64 u-cols). 8 warps 4x2, warp tile 32x32, tf32 m16n8k8.
__global__ __launch_bounds__(256) void gemm1_kernel(const float* __restrict__ x,
                                                    const float* __restrict__ w13) {
    int e = blockIdx.z;
    int cnt = g_count[e];
    int rt = blockIdx.y;
    if (rt * 128 >= cnt) return;
    int off = g_off[e];
    int ct = blockIdx.x;

    __shared__ uint32_t sA[128][36];
    __shared__ uint32_t sBg[64][36];
    __shared__ uint32_t sBu[64][36];

    int tid = threadIdx.x;
    int lane = tid & 31, wid = tid >> 5;
    int wm = wid >> 1, wn = wid & 1;
    int kq = tid & 7;        // float4 within the 32-float k slab
    int rbase = tid >> 3;    // 0..31

    int rowtok[4];
#pragma unroll
    for (int i = 0; i < 4; i++) {
        int ridx = rt * 128 + rbase + 32 * i;
        rowtok[i] = (ridx < cnt) ? (g_list_c[off + ridx] >> 1) : -1;
    }
    const float* bgp = w13 + ((size_t)e * 2 * INTER + (size_t)ct * 64) * HID;
    const float* bup = bgp + (size_t)INTER * HID;

    float cg[2][4][4], cu[2][4][4];
#pragma unroll
    for (int mt = 0; mt < 2; mt++)
#pragma unroll
        for (int nt = 0; nt < 4; nt++)
#pragma unroll
            for (int q = 0; q < 4; q++) { cg[mt][nt][q] = 0.f; cu[mt][nt][q] = 0.f; }

    for (int k0 = 0; k0 < HID; k0 += 32) {
        __syncthreads();
#pragma unroll
        for (int i = 0; i < 4; i++) {
            float4 v = make_float4(0.f, 0.f, 0.f, 0.f);
            if (rowtok[i] >= 0)
                v = *(const float4*)(x + (size_t)rowtok[i] * HID + k0 + kq * 4);
            int m = rbase + 32 * i;
            sA[m][kq * 4 + 0] = f2tf(v.x); sA[m][kq * 4 + 1] = f2tf(v.y);
            sA[m][kq * 4 + 2] = f2tf(v.z); sA[m][kq * 4 + 3] = f2tf(v.w);
        }
#pragma unroll
        for (int i = 0; i < 2; i++) {
            int n = rbase + 32 * i;
            float4 vg = *(const float4*)(bgp + (size_t)n * HID + k0 + kq * 4);
            float4 vu = *(const float4*)(bup + (size_t)n * HID + k0 + kq * 4);
            sBg[n][kq * 4 + 0] = f2tf(vg.x); sBg[n][kq * 4 + 1] = f2tf(vg.y);
            sBg[n][kq * 4 + 2] = f2tf(vg.z); sBg[n][kq * 4 + 3] = f2tf(vg.w);
            sBu[n][kq * 4 + 0] = f2tf(vu.x); sBu[n][kq * 4 + 1] = f2tf(vu.y);
            sBu[n][kq * 4 + 2] = f2tf(vu.z); sBu[n][kq * 4 + 3] = f2tf(vu.w);
        }
        __syncthreads();
#pragma unroll
        for (int ks = 0; ks < 4; ks++) {
            int kb = ks * 8 + (lane & 3);
            uint32_t af[2][4];
#pragma unroll
            for (int mt = 0; mt < 2; mt++) {
                int r = wm * 32 + mt * 16 + (lane >> 2);
                af[mt][0] = sA[r][kb];     af[mt][1] = sA[r + 8][kb];
                af[mt][2] = sA[r][kb + 4]; af[mt][3] = sA[r + 8][kb + 4];
            }
#pragma unroll
            for (int nt = 0; nt < 4; nt++) {
                int n = wn * 32 + nt * 8 + (lane >> 2);
                uint32_t bg[2] = { sBg[n][kb], sBg[n][kb + 4] };
                uint32_t bu[2] = { sBu[n][kb], sBu[n][kb + 4] };
#pragma unroll
                for (int mt = 0; mt < 2; mt++) {
                    mma8(cg[mt][nt], af[mt], bg);
                    mma8(cu[mt][nt], af[mt], bu);
                }
            }
        }
    }
    // epilogue: h = silu(g) * u
#pragma unroll
    for (int mt = 0; mt < 2; mt++) {
        int rb = wm * 32 + mt * 16 + (lane >> 2);
#pragma unroll
        for (int half = 0; half < 2; half++) {
            int ridx = rt * 128 + rb + half * 8;
            if (ridx < cnt) {
                float* hp = g_h + (size_t)(off + ridx) * INTER + (size_t)ct * 64;
#pragma unroll
                for (int nt = 0; nt < 4; nt++) {
                    int cc = wn * 32 + nt * 8 + (lane & 3) * 2;
                    float gv0 = cg[mt][nt][half * 2 + 0], gv1 = cg[mt][nt][half * 2 + 1];
                    float uv0 = cu[mt][nt][half * 2 + 0], uv1 = cu[mt][nt][half * 2 + 1];
                    hp[cc]     = gv0 * (1.f / (1.f + __expf(-gv0))) * uv0;
                    hp[cc + 1] = gv1 * (1.f / (1.f + __expf(-gv1))) * uv1;
                }
            }
        }
    }
}

// ---------------- 6. GEMM2: y[c] = w_c * (h W2^T) ----------------
// Block 128x128, 8 warps 4x2, warp tile 32x64.
__global__ __launch_bounds__(256) void gemm2_kernel(const float* __restrict__ w2) {
    int e = blockIdx.z;
    int cnt = g_count[e];
    int rt = blockIdx.y;
    if (rt * 128 >= cnt) return;
    int off = g_off[e];
    int ctn = blockIdx.x;

    __shared__ uint32_t sA[128][36];
    __shared__ uint32_t sB[128][36];

    int tid = threadIdx.x;
    int lane = tid & 31, wid = tid >> 5;
    int wm = wid >> 1, wn = wid & 1;
    int kq = tid & 7;
    int rbase = tid >> 3;

    int rowvalid[4];
#pragma unroll
    for (int i = 0; i < 4; i++)
        rowvalid[i] = ((rt * 128 + rbase + 32 * i) < cnt);

    const float* bp = w2 + ((size_t)e * HID + (size_t)ctn * 128) * INTER;

    float acc[2][8][4];
#pragma unroll
    for (int mt = 0; mt < 2; mt++)
#pragma unroll
        for (int nt = 0; nt < 8; nt++)
#pragma unroll
            for (int q = 0; q < 4; q++) acc[mt][nt][q] = 0.f;

    for (int k0 = 0; k0 < INTER; k0 += 32) {
        __syncthreads();
#pragma unroll
        for (int i = 0; i < 4; i++) {
            int m = rbase + 32 * i;
            float4 v = make_float4(0.f, 0.f, 0.f, 0.f);
            if (rowvalid[i])
                v = *(const float4*)(g_h + (size_t)(off + rt * 128 + m) * INTER + k0 + kq * 4);
            sA[m][kq * 4 + 0] = f2tf(v.x); sA[m][kq * 4 + 1] = f2tf(v.y);
            sA[m][kq * 4 + 2] = f2tf(v.z); sA[m][kq * 4 + 3] = f2tf(v.w);
        }
#pragma unroll
        for (int i = 0; i < 4; i++) {
            int n = rbase + 32 * i;
            float4 v = *(const float4*)(bp + (size_t)n * INTER + k0 + kq * 4);
            sB[n][kq * 4 + 0] = f2tf(v.x); sB[n][kq * 4 + 1] = f2tf(v.y);
            sB[n][kq * 4 + 2] = f2tf(v.z); sB[n][kq * 4 + 3] = f2tf(v.w);
        }
        __syncthreads();
#pragma unroll
        for (int ks = 0; ks < 4; ks++) {
            int kb = ks * 8 + (lane & 3);
            uint32_t af[2][4];
#pragma unroll
            for (int mt = 0; mt < 2; mt++) {
                int r = wm * 32 + mt * 16 + (lane >> 2);
                af[mt][0] = sA[r][kb];     af[mt][1] = sA[r + 8][kb];
                af[mt][2] = sA[r][kb + 4]; af[mt][3] = sA[r + 8][kb + 4];
            }
#pragma unroll
            for (int nt = 0; nt < 8; nt++) {
                int n = wn * 64 + nt * 8 + (lane >> 2);
                uint32_t bf[2] = { sB[n][kb], sB[n][kb + 4] };
#pragma unroll
                for (int mt = 0; mt < 2; mt++)
                    mma8(acc[mt][nt], af[mt], bf);
            }
        }
    }
    // epilogue: weighted write into per-(token,slot) scratch
#pragma unroll
    for (int mt = 0; mt < 2; mt++) {
        int rb = wm * 32 + mt * 16 + (lane >> 2);
#pragma unroll
        for (int half = 0; half < 2; half++) {
            int ridx = rt * 128 + rb + half * 8;
            if (ridx < cnt) {
                float w = g_list_w[off + ridx];
                int   c = g_list_c[off + ridx];
                float* yp = g_y + (size_t)c * HID + (size_t)ctn * 128;
#pragma unroll
                for (int nt = 0; nt < 8; nt++) {
                    int cc = wn * 64 + nt * 8 + (lane & 3) * 2;
                    yp[cc]     = w * acc[mt][nt][half * 2 + 0];
                    yp[cc + 1] = w * acc[mt][nt][half * 2 + 1];
                }
            }
        }
    }
}

// ---------------- 7. combine: out[t] = y[2t] + y[2t+1] ----------------
__global__ void combine_kernel(float* __restrict__ out) {
    size_t idx = (size_t)blockIdx.x * blockDim.x + threadIdx.x;
    const size_t n4 = (size_t)NTOK * HID / 4;
    if (idx >= n4) return;
    size_t t = idx / (HID / 4);
    size_t j = idx % (HID / 4);
    const float4* y4 = (const float4*)g_y;
    float4 a = y4[(t * 2) * (HID / 4) + j];
    float4 b = y4[(t * 2 + 1) * (HID / 4) + j];
    float4 o;
    o.x = a.x + b.x; o.y = a.y + b.y; o.z = a.z + b.z; o.w = a.w + b.w;
    ((float4*)out)[idx] = o;
}

// ---------------- launch ----------------
extern "C" void kernel_launch(void* const* d_in, const int* in_sizes, int n_in,
                              void* d_out, int out_size) {
    const float* x   = (const float*)d_in[0];
    const float* gw  = (const float*)d_in[1];
    const float* w13 = (const float*)d_in[2];
    const float* w2  = (const float*)d_in[3];
    float* out = (float*)d_out;

    reset_kernel<<<1, 32>>>();
    gate_kernel<<<NTOK / 8, 256>>>(x, gw);
    offsets_kernel<<<1, 1>>>();
    scatter_kernel<<<NTOK / 256, 256>>>();
    gemm1_kernel<<<dim3(INTER / 64, NTOK / 128, NE), 256>>>(x, w13);
    gemm2_kernel<<<dim3(HID / 128, NTOK / 128, NE), 256>>>(w2);
    combine_kernel<<<(NTOK * HID / 4) / 256, 256>>>(out);
}

// round 2
// speedup vs baseline: 1.0845x; 1.0845x over previous
#include <cuda_runtime.h>
#include <cstdint>
#include <cstddef>

#define NE    8
#define HID   2048
#define INTER 2816
#define NTOK  8192
#define MAXENT (NTOK * 2)

// ---------------- scratch (device globals; no runtime allocation) ----------------
__device__ int   g_count[NE];
__device__ int   g_cursor[NE];
__device__ int   g_off[NE];
__device__ int   g_tok_e[NTOK][2];
__device__ float g_tok_w[NTOK][2];
__device__ int   g_list_c[MAXENT];    // token*2 + slot
__device__ float g_list_w[MAXENT];
__device__ float g_h[(size_t)MAXENT * INTER];   // ~184 MB
__device__ float g_y[(size_t)MAXENT * HID];     // ~134 MB

// ---------------- helpers ----------------
__device__ __forceinline__ uint32_t f2tf(float x) {
    uint32_t r;
    asm("cvt.rna.tf32.f32 %0, %1;" : "=r"(r) : "f"(x));
    return r;
}

__device__ __forceinline__ void mma8(float* d, const uint32_t* a, const uint32_t* b) {
    asm volatile(
        "mma.sync.aligned.m16n8k8.row.col.f32.tf32.tf32.f32 "
        "{%0,%1,%2,%3}, {%4,%5,%6,%7}, {%8,%9}, {%0,%1,%2,%3};\n"
        : "+f"(d[0]), "+f"(d[1]), "+f"(d[2]), "+f"(d[3])
        : "r"(a[0]), "r"(a[1]), "r"(a[2]), "r"(a[3]),
          "r"(b[0]), "r"(b[1]));
}

// ---------------- 1. reset ----------------
__global__ void reset_kernel() {
    if (threadIdx.x < NE) g_count[threadIdx.x] = 0;
}

// ---------------- 2. gating: logits, softmax, top-2, counts ----------------
__global__ __launch_bounds__(256) void gate_kernel(const float* __restrict__ x,
                                                   const float* __restrict__ gw) {
    int warp = threadIdx.x >> 5;
    int lane = threadIdx.x & 31;
    int t = blockIdx.x * 8 + warp;
    if (t >= NTOK) return;

    const float4* xp = (const float4*)(x + (size_t)t * HID);
    float acc[NE];
#pragma unroll
    for (int e = 0; e < NE; e++) acc[e] = 0.f;

    for (int kk = 0; kk < HID / 4; kk += 32) {
        float4 xv = xp[kk + lane];
#pragma unroll
        for (int e = 0; e < NE; e++) {
            float4 g = ((const float4*)(gw + (size_t)e * HID))[kk + lane];
            acc[e] += xv.x * g.x + xv.y * g.y + xv.z * g.z + xv.w * g.w;
        }
    }
#pragma unroll
    for (int e = 0; e < NE; e++) {
#pragma unroll
        for (int o = 16; o > 0; o >>= 1)
            acc[e] += __shfl_xor_sync(0xffffffffu, acc[e], o);
    }
    if (lane == 0) {
        float mx = acc[0];
#pragma unroll
        for (int e = 1; e < NE; e++) mx = fmaxf(mx, acc[e]);
        float p[NE], s = 0.f;
#pragma unroll
        for (int e = 0; e < NE; e++) { p[e] = __expf(acc[e] - mx); s += p[e]; }
        float inv = 1.f / s;
        int i0 = 0; float v0 = p[0];
#pragma unroll
        for (int e = 1; e < NE; e++) if (p[e] > v0) { v0 = p[e]; i0 = e; }
        int i1 = -1; float v1 = -1.f;
#pragma unroll
        for (int e = 0; e < NE; e++) if (e != i0 && p[e] > v1) { v1 = p[e]; i1 = e; }
        g_tok_e[t][0] = i0; g_tok_e[t][1] = i1;
        g_tok_w[t][0] = v0 * inv; g_tok_w[t][1] = v1 * inv;
        atomicAdd(&g_count[i0], 1);
        atomicAdd(&g_count[i1], 1);
    }
}

// ---------------- 3. offsets ----------------
__global__ void offsets_kernel() {
    if (threadIdx.x == 0 && blockIdx.x == 0) {
        int s = 0;
        for (int e = 0; e < NE; e++) {
            g_off[e] = s;
            s += g_count[e];
            g_cursor[e] = 0;
        }
    }
}

// ---------------- 4. scatter tokens into packed per-expert lists ----------------
__global__ void scatter_kernel() {
    int t = blockIdx.x * blockDim.x + threadIdx.x;
    if (t >= NTOK) return;
#pragma unroll
    for (int s = 0; s < 2; s++) {
        int e = g_tok_e[t][s];
        int pos = atomicAdd(&g_cursor[e], 1);
        int idx = g_off[e] + pos;
        g_list_c[idx] = t * 2 + s;
        g_list_w[idx] = g_tok_w[t][s];
    }
}

// ---------------- 5. GEMM1: h = silu(X W_g^T) * (X W_u^T), gathered rows ----------------
// Block: 128 rows x (64 g-cols + 64 u-cols). 8 warps 4x2, warp tile 32x32, tf32 m16n8k8.
// Double-buffered smem (dynamic, 73728 B), register-prefetch pipeline, 1 sync/iter.
#define G1_SA  0                     // [2][128][36]
#define G1_SBG 9216                  // [2][64][36]
#define G1_SBU 13824                 // [2][64][36]
#define G1_SMEM_BYTES (18432 * 4)

__global__ __launch_bounds__(256) void gemm1_kernel(const float* __restrict__ x,
                                                    const float* __restrict__ w13) {
    int e = blockIdx.z;
    int cnt = g_count[e];
    int rt = blockIdx.y;
    if (rt * 128 >= cnt) return;
    int off = g_off[e];
    int ct = blockIdx.x;

    extern __shared__ uint32_t sm[];

    int tid = threadIdx.x;
    int lane = tid & 31, wid = tid >> 5;
    int wm = wid >> 1, wn = wid & 1;
    int kq = tid & 7;        // float4 within the 32-float k slab
    int rbase = tid >> 3;    // 0..31

    int rowtok[4];
#pragma unroll
    for (int i = 0; i < 4; i++) {
        int ridx = rt * 128 + rbase + 32 * i;
        rowtok[i] = (ridx < cnt) ? (g_list_c[off + ridx] >> 1) : -1;
    }
    const float* bgp = w13 + ((size_t)e * 2 * INTER + (size_t)ct * 64) * HID;
    const float* bup = bgp + (size_t)INTER * HID;

    float cg[2][4][4], cu[2][4][4];
#pragma unroll
    for (int mt = 0; mt < 2; mt++)
#pragma unroll
        for (int nt = 0; nt < 4; nt++)
#pragma unroll
            for (int q = 0; q < 4; q++) { cg[mt][nt][q] = 0.f; cu[mt][nt][q] = 0.f; }

    float4 pa[4], pg[2], pu[2];

    // ---- prologue: load + store slab 0 ----
#pragma unroll
    for (int i = 0; i < 4; i++) {
        pa[i] = make_float4(0.f, 0.f, 0.f, 0.f);
        if (rowtok[i] >= 0)
            pa[i] = *(const float4*)(x + (size_t)rowtok[i] * HID + kq * 4);
    }
#pragma unroll
    for (int i = 0; i < 2; i++) {
        int n = rbase + 32 * i;
        pg[i] = *(const float4*)(bgp + (size_t)n * HID + kq * 4);
        pu[i] = *(const float4*)(bup + (size_t)n * HID + kq * 4);
    }
#pragma unroll
    for (int i = 0; i < 4; i++) {
        uint4 v = make_uint4(f2tf(pa[i].x), f2tf(pa[i].y), f2tf(pa[i].z), f2tf(pa[i].w));
        *(uint4*)&sm[G1_SA + (rbase + 32 * i) * 36 + kq * 4] = v;
    }
#pragma unroll
    for (int i = 0; i < 2; i++) {
        int n = rbase + 32 * i;
        uint4 vg = make_uint4(f2tf(pg[i].x), f2tf(pg[i].y), f2tf(pg[i].z), f2tf(pg[i].w));
        uint4 vu = make_uint4(f2tf(pu[i].x), f2tf(pu[i].y), f2tf(pu[i].z), f2tf(pu[i].w));
        *(uint4*)&sm[G1_SBG + n * 36 + kq * 4] = vg;
        *(uint4*)&sm[G1_SBU + n * 36 + kq * 4] = vu;
    }
    __syncthreads();

    for (int k0 = 0; k0 < HID; k0 += 32) {
        int cur = (k0 >> 5) & 1;
        bool more = (k0 + 32) < HID;
        int knext = more ? (k0 + 32) : 0;

        // front-batched prefetch of next slab (always issued; dropped if !more)
#pragma unroll
        for (int i = 0; i < 4; i++) {
            pa[i] = make_float4(0.f, 0.f, 0.f, 0.f);
            if (rowtok[i] >= 0)
                pa[i] = *(const float4*)(x + (size_t)rowtok[i] * HID + knext + kq * 4);
        }
#pragma unroll
        for (int i = 0; i < 2; i++) {
            int n = rbase + 32 * i;
            pg[i] = *(const float4*)(bgp + (size_t)n * HID + knext + kq * 4);
            pu[i] = *(const float4*)(bup + (size_t)n * HID + knext + kq * 4);
        }

        const uint32_t* A  = &sm[G1_SA  + cur * 4608];
        const uint32_t* Bg = &sm[G1_SBG + cur * 2304];
        const uint32_t* Bu = &sm[G1_SBU + cur * 2304];
#pragma unroll
        for (int ks = 0; ks < 4; ks++) {
            int kb = ks * 8 + (lane & 3);
            uint32_t af[2][4];
#pragma unroll
            for (int mt = 0; mt < 2; mt++) {
                int r = wm * 32 + mt * 16 + (lane >> 2);
                af[mt][0] = A[r * 36 + kb];           af[mt][1] = A[(r + 8) * 36 + kb];
                af[mt][2] = A[r * 36 + kb + 4];       af[mt][3] = A[(r + 8) * 36 + kb + 4];
            }
#pragma unroll
            for (int nt = 0; nt < 4; nt++) {
                int n = wn * 32 + nt * 8 + (lane >> 2);
                uint32_t bg[2] = { Bg[n * 36 + kb], Bg[n * 36 + kb + 4] };
                uint32_t bu[2] = { Bu[n * 36 + kb], Bu[n * 36 + kb + 4] };
#pragma unroll
                for (int mt = 0; mt < 2; mt++) {
                    mma8(cg[mt][nt], af[mt], bg);
                    mma8(cu[mt][nt], af[mt], bu);
                }
            }
        }

        if (more) {
            int nb = cur ^ 1;
#pragma unroll
            for (int i = 0; i < 4; i++) {
                uint4 v = make_uint4(f2tf(pa[i].x), f2tf(pa[i].y), f2tf(pa[i].z), f2tf(pa[i].w));
                *(uint4*)&sm[G1_SA + nb * 4608 + (rbase + 32 * i) * 36 + kq * 4] = v;
            }
#pragma unroll
            for (int i = 0; i < 2; i++) {
                int n = rbase + 32 * i;
                uint4 vg = make_uint4(f2tf(pg[i].x), f2tf(pg[i].y), f2tf(pg[i].z), f2tf(pg[i].w));
                uint4 vu = make_uint4(f2tf(pu[i].x), f2tf(pu[i].y), f2tf(pu[i].z), f2tf(pu[i].w));
                *(uint4*)&sm[G1_SBG + nb * 2304 + n * 36 + kq * 4] = vg;
                *(uint4*)&sm[G1_SBU + nb * 2304 + n * 36 + kq * 4] = vu;
            }
        }
        __syncthreads();
    }

    // epilogue: h = silu(g) * u
#pragma unroll
    for (int mt = 0; mt < 2; mt++) {
        int rb = wm * 32 + mt * 16 + (lane >> 2);
#pragma unroll
        for (int half = 0; half < 2; half++) {
            int ridx = rt * 128 + rb + half * 8;
            if (ridx < cnt) {
                float* hp = g_h + (size_t)(off + ridx) * INTER + (size_t)ct * 64;
#pragma unroll
                for (int nt = 0; nt < 4; nt++) {
                    int cc = wn * 32 + nt * 8 + (lane & 3) * 2;
                    float gv0 = cg[mt][nt][half * 2 + 0], gv1 = cg[mt][nt][half * 2 + 1];
                    float uv0 = cu[mt][nt][half * 2 + 0], uv1 = cu[mt][nt][half * 2 + 1];
                    hp[cc]     = gv0 * (1.f / (1.f + __expf(-gv0))) * uv0;
                    hp[cc + 1] = gv1 * (1.f / (1.f + __expf(-gv1))) * uv1;
                }
            }
        }
    }
}

// ---------------- 6. GEMM2: y[c] = w_c * (h W2^T) ----------------
// Block 128x128, 8 warps 4x2, warp tile 32x64. Double-buffered pipeline.
#define G2_SA 0                      // [2][128][36]
#define G2_SB 9216                   // [2][128][36]
#define G2_SMEM_BYTES (18432 * 4)

__global__ __launch_bounds__(256) void gemm2_kernel(const float* __restrict__ w2) {
    int e = blockIdx.z;
    int cnt = g_count[e];
    int rt = blockIdx.y;
    if (rt * 128 >= cnt) return;
    int off = g_off[e];
    int ctn = blockIdx.x;

    extern __shared__ uint32_t sm[];

    int tid = threadIdx.x;
    int lane = tid & 31, wid = tid >> 5;
    int wm = wid >> 1, wn = wid & 1;
    int kq = tid & 7;
    int rbase = tid >> 3;

    const float* ap[4];
#pragma unroll
    for (int i = 0; i < 4; i++) {
        int ridx = rt * 128 + rbase + 32 * i;
        ap[i] = (ridx < cnt) ? (g_h + (size_t)(off + ridx) * INTER) : nullptr;
    }

    const float* bp = w2 + ((size_t)e * HID + (size_t)ctn * 128) * INTER;

    float acc[2][8][4];
#pragma unroll
    for (int mt = 0; mt < 2; mt++)
#pragma unroll
        for (int nt = 0; nt < 8; nt++)
#pragma unroll
            for (int q = 0; q < 4; q++) acc[mt][nt][q] = 0.f;

    float4 pa[4], pb[4];

    // ---- prologue: slab 0 ----
#pragma unroll
    for (int i = 0; i < 4; i++) {
        pa[i] = make_float4(0.f, 0.f, 0.f, 0.f);
        if (ap[i]) pa[i] = *(const float4*)(ap[i] + kq * 4);
        pb[i] = *(const float4*)(bp + (size_t)(rbase + 32 * i) * INTER + kq * 4);
    }
#pragma unroll
    for (int i = 0; i < 4; i++) {
        int m = rbase + 32 * i;
        uint4 va = make_uint4(f2tf(pa[i].x), f2tf(pa[i].y), f2tf(pa[i].z), f2tf(pa[i].w));
        uint4 vb = make_uint4(f2tf(pb[i].x), f2tf(pb[i].y), f2tf(pb[i].z), f2tf(pb[i].w));
        *(uint4*)&sm[G2_SA + m * 36 + kq * 4] = va;
        *(uint4*)&sm[G2_SB + m * 36 + kq * 4] = vb;
    }
    __syncthreads();

    for (int k0 = 0; k0 < INTER; k0 += 32) {
        int cur = (k0 >> 5) & 1;
        bool more = (k0 + 32) < INTER;
        int knext = more ? (k0 + 32) : 0;

#pragma unroll
        for (int i = 0; i < 4; i++) {
            pa[i] = make_float4(0.f, 0.f, 0.f, 0.f);
            if (ap[i]) pa[i] = *(const float4*)(ap[i] + knext + kq * 4);
            pb[i] = *(const float4*)(bp + (size_t)(rbase + 32 * i) * INTER + knext + kq * 4);
        }

        const uint32_t* A = &sm[G2_SA + cur * 4608];
        const uint32_t* B = &sm[G2_SB + cur * 4608];
#pragma unroll
        for (int ks = 0; ks < 4; ks++) {
            int kb = ks * 8 + (lane & 3);
            uint32_t af[2][4];
#pragma unroll
            for (int mt = 0; mt < 2; mt++) {
                int r = wm * 32 + mt * 16 + (lane >> 2);
                af[mt][0] = A[r * 36 + kb];       af[mt][1] = A[(r + 8) * 36 + kb];
                af[mt][2] = A[r * 36 + kb + 4];   af[mt][3] = A[(r + 8) * 36 + kb + 4];
            }
#pragma unroll
            for (int nt = 0; nt < 8; nt++) {
                int n = wn * 64 + nt * 8 + (lane >> 2);
                uint32_t bf[2] = { B[n * 36 + kb], B[n * 36 + kb + 4] };
#pragma unroll
                for (int mt = 0; mt < 2; mt++)
                    mma8(acc[mt][nt], af[mt], bf);
            }
        }

        if (more) {
            int nb = cur ^ 1;
#pragma unroll
            for (int i = 0; i < 4; i++) {
                int m = rbase + 32 * i;
                uint4 va = make_uint4(f2tf(pa[i].x), f2tf(pa[i].y), f2tf(pa[i].z), f2tf(pa[i].w));
                uint4 vb = make_uint4(f2tf(pb[i].x), f2tf(pb[i].y), f2tf(pb[i].z), f2tf(pb[i].w));
                *(uint4*)&sm[G2_SA + nb * 4608 + m * 36 + kq * 4] = va;
                *(uint4*)&sm[G2_SB + nb * 4608 + m * 36 + kq * 4] = vb;
            }
        }
        __syncthreads();
    }

    // epilogue: weighted write into per-(token,slot) scratch
#pragma unroll
    for (int mt = 0; mt < 2; mt++) {
        int rb = wm * 32 + mt * 16 + (lane >> 2);
#pragma unroll
        for (int half = 0; half < 2; half++) {
            int ridx = rt * 128 + rb + half * 8;
            if (ridx < cnt) {
                float w = g_list_w[off + ridx];
                int   c = g_list_c[off + ridx];
                float* yp = g_y + (size_t)c * HID + (size_t)ctn * 128;
#pragma unroll
                for (int nt = 0; nt < 8; nt++) {
                    int cc = wn * 64 + nt * 8 + (lane & 3) * 2;
                    yp[cc]     = w * acc[mt][nt][half * 2 + 0];
                    yp[cc + 1] = w * acc[mt][nt][half * 2 + 1];
                }
            }
        }
    }
}

// ---------------- 7. combine: out[t] = y[2t] + y[2t+1] ----------------
__global__ void combine_kernel(float* __restrict__ out) {
    size_t idx = (size_t)blockIdx.x * blockDim.x + threadIdx.x;
    const size_t n4 = (size_t)NTOK * HID / 4;
    if (idx >= n4) return;
    size_t t = idx / (HID / 4);
    size_t j = idx % (HID / 4);
    const float4* y4 = (const float4*)g_y;
    float4 a = y4[(t * 2) * (HID / 4) + j];
    float4 b = y4[(t * 2 + 1) * (HID / 4) + j];
    float4 o;
    o.x = a.x + b.x; o.y = a.y + b.y; o.z = a.z + b.z; o.w = a.w + b.w;
    ((float4*)out)[idx] = o;
}

// ---------------- launch ----------------
extern "C" void kernel_launch(void* const* d_in, const int* in_sizes, int n_in,
                              void* d_out, int out_size) {
    const float* x   = (const float*)d_in[0];
    const float* gw  = (const float*)d_in[1];
    const float* w13 = (const float*)d_in[2];
    const float* w2  = (const float*)d_in[3];
    float* out = (float*)d_out;

    cudaFuncSetAttribute(gemm1_kernel, cudaFuncAttributeMaxDynamicSharedMemorySize, G1_SMEM_BYTES);
    cudaFuncSetAttribute(gemm2_kernel, cudaFuncAttributeMaxDynamicSharedMemorySize, G2_SMEM_BYTES);

    reset_kernel<<<1, 32>>>();
    gate_kernel<<<NTOK / 8, 256>>>(x, gw);
    offsets_kernel<<<1, 1>>>();
    scatter_kernel<<<NTOK / 256, 256>>>();
    gemm1_kernel<<<dim3(INTER / 64, NTOK / 128, NE), 256, G1_SMEM_BYTES>>>(x, w13);
    gemm2_kernel<<<dim3(HID / 128, NTOK / 128, NE), 256, G2_SMEM_BYTES>>>(w2);
    combine_kernel<<<(NTOK * HID / 4) / 256, 256>>>(out);
}

// round 4
// speedup vs baseline: 1.8547x; 1.7102x over previous
#include <cuda_runtime.h>
#include <cstdint>
#include <cstddef>

#define NE    8
#define HID   2048
#define INTER 2816
#define NTOK  8192
#define MAXENT (NTOK * 2)
#define CAP   16384            // per-expert worst-case rows

// ---------------- scratch (device globals; no runtime allocation) ----------------
__device__ int   g_cursor[NE];
__device__ int   g_list_c[NE * CAP];           // token*2 + slot
__device__ float g_list_w[NE * CAP];
__device__ float c_x[(size_t)NTOK * HID];            // tf32-rounded x   (67 MB)
__device__ float c_w13[(size_t)NE * 2 * INTER * HID];// tf32-rounded w13 (369 MB)
__device__ float c_w2[(size_t)NE * HID * INTER];     // tf32-rounded w2  (184 MB)
__device__ float g_h[(size_t)NE * CAP * INTER];      // padded per-expert h (1.47 GB)
__device__ float g_y[(size_t)MAXENT * HID];          // per-(token,slot) y (134 MB)

// ---------------- helpers ----------------
__device__ __forceinline__ uint32_t f2tf(float x) {
    uint32_t r;
    asm("cvt.rna.tf32.f32 %0, %1;" : "=r"(r) : "f"(x));
    return r;
}
__device__ __forceinline__ uint32_t smem_u32(const void* p) {
    uint32_t a;
    asm("{ .reg .u64 t; cvta.to.shared.u64 t, %1; cvt.u32.u64 %0, t; }" : "=r"(a) : "l"(p));
    return a;
}
__device__ __forceinline__ void cpasync16(uint32_t dst, const void* src, int srcsize) {
    asm volatile("cp.async.cg.shared.global [%0], [%1], 16, %2;"
                 :: "r"(dst), "l"(src), "r"(srcsize) : "memory");
}
#define CP_COMMIT() asm volatile("cp.async.commit_group;" ::: "memory")
#define CP_WAIT1()  asm volatile("cp.async.wait_group 1;" ::: "memory")
#define CP_WAIT0()  asm volatile("cp.async.wait_group 0;" ::: "memory")

__device__ __forceinline__ void mma8(float* d, const uint32_t* a, const uint32_t* b) {
    asm volatile(
        "mma.sync.aligned.m16n8k8.row.col.f32.tf32.tf32.f32 "
        "{%0,%1,%2,%3}, {%4,%5,%6,%7}, {%8,%9}, {%0,%1,%2,%3};\n"
        : "+f"(d[0]), "+f"(d[1]), "+f"(d[2]), "+f"(d[3])
        : "r"(a[0]), "r"(a[1]), "r"(a[2]), "r"(a[3]),
          "r"(b[0]), "r"(b[1]));
}

// swizzled 32-bit smem load from a 128-rowbyte tile: element (r, kword)
#define LDSW(st, r, k) (*(const uint32_t*)((st) + (size_t)(r) * 128 + (((k) * 4) ^ (((r) & 7) << 4))))

#define STAGE_BYTES 32768      // A 16KB + B 16KB
#define GEMM_SMEM (2 * STAGE_BYTES)

// ---------------- 0a. convert w13 (+ reset cursors) ----------------
__global__ __launch_bounds__(256) void conv_w13_kernel(const float* __restrict__ w13) {
    if (blockIdx.x == 0 && threadIdx.x < NE) g_cursor[threadIdx.x] = 0;
    const size_t n4 = (size_t)NE * 2 * INTER * HID / 4;
    for (size_t i = (size_t)blockIdx.x * blockDim.x + threadIdx.x; i < n4;
         i += (size_t)gridDim.x * blockDim.x) {
        float4 v = ((const float4*)w13)[i];
        uint4 o = make_uint4(f2tf(v.x), f2tf(v.y), f2tf(v.z), f2tf(v.w));
        ((uint4*)c_w13)[i] = o;
    }
}

// ---------------- 0b. convert w2 + x ----------------
__global__ __launch_bounds__(256) void conv_w2x_kernel(const float* __restrict__ w2,
                                                       const float* __restrict__ x) {
    const size_t nw = (size_t)NE * HID * INTER / 4;
    for (size_t i = (size_t)blockIdx.x * blockDim.x + threadIdx.x; i < nw;
         i += (size_t)gridDim.x * blockDim.x) {
        float4 v = ((const float4*)w2)[i];
        ((uint4*)c_w2)[i] = make_uint4(f2tf(v.x), f2tf(v.y), f2tf(v.z), f2tf(v.w));
    }
    const size_t nx = (size_t)NTOK * HID / 4;
    for (size_t i = (size_t)blockIdx.x * blockDim.x + threadIdx.x; i < nx;
         i += (size_t)gridDim.x * blockDim.x) {
        float4 v = ((const float4*)x)[i];
        ((uint4*)c_x)[i] = make_uint4(f2tf(v.x), f2tf(v.y), f2tf(v.z), f2tf(v.w));
    }
}

// ---------------- 1. gating + scatter (fused) ----------------
__global__ __launch_bounds__(256) void gate_kernel(const float* __restrict__ x,
                                                   const float* __restrict__ gw) {
    int warp = threadIdx.x >> 5;
    int lane = threadIdx.x & 31;
    int t = blockIdx.x * 8 + warp;
    if (t >= NTOK) return;

    const float4* xp = (const float4*)(x + (size_t)t * HID);
    float acc[NE];
#pragma unroll
    for (int e = 0; e < NE; e++) acc[e] = 0.f;

    for (int kk = 0; kk < HID / 4; kk += 32) {
        float4 xv = xp[kk + lane];
#pragma unroll
        for (int e = 0; e < NE; e++) {
            float4 g = ((const float4*)(gw + (size_t)e * HID))[kk + lane];
            acc[e] += xv.x * g.x + xv.y * g.y + xv.z * g.z + xv.w * g.w;
        }
    }
#pragma unroll
    for (int e = 0; e < NE; e++) {
#pragma unroll
        for (int o = 16; o > 0; o >>= 1)
            acc[e] += __shfl_xor_sync(0xffffffffu, acc[e], o);
    }
    if (lane == 0) {
        float mx = acc[0];
#pragma unroll
        for (int e = 1; e < NE; e++) mx = fmaxf(mx, acc[e]);
        float p[NE], s = 0.f;
#pragma unroll
        for (int e = 0; e < NE; e++) { p[e] = __expf(acc[e] - mx); s += p[e]; }
        float inv = 1.f / s;
        int i0 = 0; float v0 = p[0];
#pragma unroll
        for (int e = 1; e < NE; e++) if (p[e] > v0) { v0 = p[e]; i0 = e; }
        int i1 = -1; float v1 = -1.f;
#pragma unroll
        for (int e = 0; e < NE; e++) if (e != i0 && p[e] > v1) { v1 = p[e]; i1 = e; }
        int pos0 = atomicAdd(&g_cursor[i0], 1);
        g_list_c[i0 * CAP + pos0] = t * 2;
        g_list_w[i0 * CAP + pos0] = v0 * inv;
        int pos1 = atomicAdd(&g_cursor[i1], 1);
        g_list_c[i1 * CAP + pos1] = t * 2 + 1;
        g_list_w[i1 * CAP + pos1] = v1 * inv;
    }
}

// ---------------- 2. GEMM1: h = silu(X Wg^T) * (X Wu^T) ----------------
// tile 128 rows x (64 g + 64 u cols); 8 warps 4x2, warp 32x(32g+32u); cp.async 2-stage.
#define NS1 (HID / 32)   // 64

__global__ __launch_bounds__(256) void gemm1_kernel() {
    int e = blockIdx.z;
    int cnt = g_cursor[e];
    int rt = blockIdx.y;
    if (rt * 128 >= cnt) return;
    int ct = blockIdx.x;

    extern __shared__ char sm[];
    uint32_t sbase = smem_u32(sm);

    int tid = threadIdx.x;
    int lane = tid & 31, wid = tid >> 5;
    int wm = wid >> 1, wn = wid & 1;

    // loader mapping: 4 A-chunks + 4 B-chunks of 16B per thread per slab
    const float* asrc[4];
    const float* bsrc[4];
    int assz[4];
    uint32_t dsto[4];
#pragma unroll
    for (int i = 0; i < 4; i++) {
        int idx = i * 256 + tid;
        int r = idx >> 3;            // 0..127
        int q = idx & 7;             // 16B chunk in 128B row
        int ridx = rt * 128 + r;
        int tok = (ridx < cnt) ? (g_list_c[e * CAP + ridx] >> 1) : 0;
        asrc[i] = c_x + (size_t)tok * HID + q * 4;
        assz[i] = (ridx < cnt) ? 16 : 0;
        int grow = (r < 64) ? (ct * 64 + r) : (INTER + ct * 64 + (r - 64));
        bsrc[i] = c_w13 + ((size_t)e * 2 * INTER + grow) * HID + q * 4;
        dsto[i] = (uint32_t)(r * 128 + ((q * 16) ^ ((r & 7) << 4)));
    }

    float cg[2][4][4], cu[2][4][4];
#pragma unroll
    for (int mt = 0; mt < 2; mt++)
#pragma unroll
        for (int nt = 0; nt < 4; nt++)
#pragma unroll
            for (int q = 0; q < 4; q++) { cg[mt][nt][q] = 0.f; cu[mt][nt][q] = 0.f; }

    // prologue: slab 0
#pragma unroll
    for (int i = 0; i < 4; i++) {
        cpasync16(sbase + dsto[i], asrc[i], assz[i]);
        cpasync16(sbase + 16384 + dsto[i], bsrc[i], 16);
    }
    CP_COMMIT();

    for (int s = 0; s < NS1; s++) {
        if (s + 1 < NS1) {
            uint32_t sb = sbase + ((s + 1) & 1) * STAGE_BYTES;
            int k0 = (s + 1) * 32;
#pragma unroll
            for (int i = 0; i < 4; i++) {
                cpasync16(sb + dsto[i], asrc[i] + k0, assz[i]);
                cpasync16(sb + 16384 + dsto[i], bsrc[i] + k0, 16);
            }
            CP_COMMIT();
            CP_WAIT1();
        } else {
            CP_WAIT0();
        }
        __syncthreads();

        const char* stA = sm + (s & 1) * STAGE_BYTES;
        const char* stB = stA + 16384;
#pragma unroll
        for (int ks = 0; ks < 4; ks++) {
            int kb = ks * 8 + (lane & 3);
            uint32_t af[2][4];
#pragma unroll
            for (int mt = 0; mt < 2; mt++) {
                int r0 = wm * 32 + mt * 16 + (lane >> 2);
                af[mt][0] = LDSW(stA, r0, kb);     af[mt][1] = LDSW(stA, r0 + 8, kb);
                af[mt][2] = LDSW(stA, r0, kb + 4); af[mt][3] = LDSW(stA, r0 + 8, kb + 4);
            }
#pragma unroll
            for (int nt = 0; nt < 4; nt++) {
                int n = wn * 32 + nt * 8 + (lane >> 2);
                uint32_t bg[2] = { LDSW(stB, n, kb),      LDSW(stB, n, kb + 4) };
                uint32_t bu[2] = { LDSW(stB, n + 64, kb), LDSW(stB, n + 64, kb + 4) };
#pragma unroll
                for (int mt = 0; mt < 2; mt++) {
                    mma8(cg[mt][nt], af[mt], bg);
                    mma8(cu[mt][nt], af[mt], bu);
                }
            }
        }
        __syncthreads();
    }

    // epilogue: h = silu(g) * u, stored tf32-rounded
#pragma unroll
    for (int mt = 0; mt < 2; mt++) {
        int rb = wm * 32 + mt * 16 + (lane >> 2);
#pragma unroll
        for (int half = 0; half < 2; half++) {
            int ridx = rt * 128 + rb + half * 8;
            if (ridx < cnt) {
                float* hp = g_h + ((size_t)e * CAP + ridx) * INTER + (size_t)ct * 64;
#pragma unroll
                for (int nt = 0; nt < 4; nt++) {
                    int cc = wn * 32 + nt * 8 + (lane & 3) * 2;
                    float gv0 = cg[mt][nt][half * 2 + 0], gv1 = cg[mt][nt][half * 2 + 1];
                    float uv0 = cu[mt][nt][half * 2 + 0], uv1 = cu[mt][nt][half * 2 + 1];
                    float h0 = gv0 * (1.f / (1.f + __expf(-gv0))) * uv0;
                    float h1 = gv1 * (1.f / (1.f + __expf(-gv1))) * uv1;
                    hp[cc]     = __uint_as_float(f2tf(h0));
                    hp[cc + 1] = __uint_as_float(f2tf(h1));
                }
            }
        }
    }
}

// ---------------- 3. GEMM2: y[c] = w_c * (h W2^T) ----------------
// tile 128x128; 8 warps 4x2, warp 32x64; cp.async 2-stage.
#define NS2 (INTER / 32)  // 88

__global__ __launch_bounds__(256) void gemm2_kernel() {
    int e = blockIdx.z;
    int cnt = g_cursor[e];
    int rt = blockIdx.y;
    if (rt * 128 >= cnt) return;
    int ctn = blockIdx.x;

    extern __shared__ char sm[];
    uint32_t sbase = smem_u32(sm);

    int tid = threadIdx.x;
    int lane = tid & 31, wid = tid >> 5;
    int wm = wid >> 1, wn = wid & 1;

    const float* asrc[4];
    const float* bsrc[4];
    int assz[4];
    uint32_t dsto[4];
#pragma unroll
    for (int i = 0; i < 4; i++) {
        int idx = i * 256 + tid;
        int r = idx >> 3;
        int q = idx & 7;
        int ridx = rt * 128 + r;
        asrc[i] = g_h + ((size_t)e * CAP + ridx) * INTER + q * 4;
        assz[i] = (ridx < cnt) ? 16 : 0;
        bsrc[i] = c_w2 + ((size_t)e * HID + ctn * 128 + r) * INTER + q * 4;
        dsto[i] = (uint32_t)(r * 128 + ((q * 16) ^ ((r & 7) << 4)));
    }

    float acc[2][8][4];
#pragma unroll
    for (int mt = 0; mt < 2; mt++)
#pragma unroll
        for (int nt = 0; nt < 8; nt++)
#pragma unroll
            for (int q = 0; q < 4; q++) acc[mt][nt][q] = 0.f;

#pragma unroll
    for (int i = 0; i < 4; i++) {
        cpasync16(sbase + dsto[i], asrc[i], assz[i]);
        cpasync16(sbase + 16384 + dsto[i], bsrc[i], 16);
    }
    CP_COMMIT();

    for (int s = 0; s < NS2; s++) {
        if (s + 1 < NS2) {
            uint32_t sb = sbase + ((s + 1) & 1) * STAGE_BYTES;
            int k0 = (s + 1) * 32;
#pragma unroll
            for (int i = 0; i < 4; i++) {
                cpasync16(sb + dsto[i], asrc[i] + k0, assz[i]);
                cpasync16(sb + 16384 + dsto[i], bsrc[i] + k0, 16);
            }
            CP_COMMIT();
            CP_WAIT1();
        } else {
            CP_WAIT0();
        }
        __syncthreads();

        const char* stA = sm + (s & 1) * STAGE_BYTES;
        const char* stB = stA + 16384;
#pragma unroll
        for (int ks = 0; ks < 4; ks++) {
            int kb = ks * 8 + (lane & 3);
            uint32_t af[2][4];
#pragma unroll
            for (int mt = 0; mt < 2; mt++) {
                int r0 = wm * 32 + mt * 16 + (lane >> 2);
                af[mt][0] = LDSW(stA, r0, kb);     af[mt][1] = LDSW(stA, r0 + 8, kb);
                af[mt][2] = LDSW(stA, r0, kb + 4); af[mt][3] = LDSW(stA, r0 + 8, kb + 4);
            }
#pragma unroll
            for (int nt = 0; nt < 8; nt++) {
                int n = wn * 64 + nt * 8 + (lane >> 2);
                uint32_t bf[2] = { LDSW(stB, n, kb), LDSW(stB, n, kb + 4) };
#pragma unroll
                for (int mt = 0; mt < 2; mt++)
                    mma8(acc[mt][nt], af[mt], bf);
            }
        }
        __syncthreads();
    }

    // epilogue: weighted write into per-(token,slot) scratch
#pragma unroll
    for (int mt = 0; mt < 2; mt++) {
        int rb = wm * 32 + mt * 16 + (lane >> 2);
#pragma unroll
        for (int half = 0; half < 2; half++) {
            int ridx = rt * 128 + rb + half * 8;
            if (ridx < cnt) {
                float w = g_list_w[e * CAP + ridx];
                int   c = g_list_c[e * CAP + ridx];
                float* yp = g_y + (size_t)c * HID + (size_t)ctn * 128;
#pragma unroll
                for (int nt = 0; nt < 8; nt++) {
                    int cc = wn * 64 + nt * 8 + (lane & 3) * 2;
                    yp[cc]     = w * acc[mt][nt][half * 2 + 0];
                    yp[cc + 1] = w * acc[mt][nt][half * 2 + 1];
                }
            }
        }
    }
}

// ---------------- 4. combine: out[t] = y[2t] + y[2t+1] ----------------
__global__ void combine_kernel(float* __restrict__ out) {
    size_t idx = (size_t)blockIdx.x * blockDim.x + threadIdx.x;
    const size_t n4 = (size_t)NTOK * HID / 4;
    if (idx >= n4) return;
    size_t t = idx / (HID / 4);
    size_t j = idx % (HID / 4);
    const float4* y4 = (const float4*)g_y;
    float4 a = y4[(t * 2) * (HID / 4) + j];
    float4 b = y4[(t * 2 + 1) * (HID / 4) + j];
    float4 o;
    o.x = a.x + b.x; o.y = a.y + b.y; o.z = a.z + b.z; o.w = a.w + b.w;
    ((float4*)out)[idx] = o;
}

// ---------------- launch ----------------
extern "C" void kernel_launch(void* const* d_in, const int* in_sizes, int n_in,
                              void* d_out, int out_size) {
    const float* x   = (const float*)d_in[0];
    const float* gw  = (const float*)d_in[1];
    const float* w13 = (const float*)d_in[2];
    const float* w2  = (const float*)d_in[3];
    float* out = (float*)d_out;

    cudaFuncSetAttribute(gemm1_kernel, cudaFuncAttributeMaxDynamicSharedMemorySize, GEMM_SMEM);
    cudaFuncSetAttribute(gemm2_kernel, cudaFuncAttributeMaxDynamicSharedMemorySize, GEMM_SMEM);

    conv_w13_kernel<<<2048, 256>>>(w13);                        // launch 0
    conv_w2x_kernel<<<2048, 256>>>(w2, x);                      // launch 1
    gate_kernel<<<NTOK / 8, 256>>>(x, gw);                      // launch 2
    gemm1_kernel<<<dim3(INTER / 64, CAP / 128, NE), 256, GEMM_SMEM>>>();  // launch 3 (ncu)
    gemm2_kernel<<<dim3(HID / 128, CAP / 128, NE), 256, GEMM_SMEM>>>();   // launch 4
    combine_kernel<<<(NTOK * HID / 4) / 256, 256>>>(out);       // launch 5
}